// round 9
// baseline (speedup 1.0000x reference)
#include <cuda_runtime.h>
#include <cstdint>

// CenterLoss: BATCH=4096, FEAT_DIM=256, NUM_CLASSES=8192
#define BATCH       4096
#define FEAT_DIM    256
#define NUM_CLASSES 8192
#define NBLOCKS     512
#define NTHREADS    256            // 8 warps/CTA, warp-per-sample
#define LSCALE      65536.0f       // 2^16 per-lane fixed-point scale
#define SCALE       16777216.0     // 2^24 sample fixed-point scale
#define CNT_SHIFT   50             // count lives in bits [50..63]
#define SUM_MASK    ((1ull << CNT_SHIFT) - 1ull)

// Single packed global accumulator: bits [0,50) sum, bits [50,64) CTA count.
__device__ unsigned long long g_acc = 0ull;

__global__ void __launch_bounds__(NTHREADS) center_loss_fused(
    const float* __restrict__ x,
    const void*  __restrict__ labels_raw,
    const float* __restrict__ centers,
    float*       __restrict__ out)
{
    const int lane = threadIdx.x & 31;
    const int warp = threadIdx.x >> 5;            // 0..7
    const int s    = blockIdx.x * 8 + warp;       // sample id 0..4095

    // Packed per-CTA accumulator: bits [0,50) sum, bits [50,64) warp count.
    __shared__ unsigned long long cta_acc;
    if (threadIdx.x == 0) cta_acc = 0ull;
    __syncthreads();   // off critical path: completes while loads in flight

    // ---- dtype probe: words 0..7 (one 128B line, warp-uniform -> L2
    // broadcast; concurrent with label + x loads). i64 => odd words zero.
    // False-i64 under i32: labels[1,3,5,7]==0, p = 8192^-4 ~ 2e-16.
    const int4 q0 = ((const int4*)labels_raw)[0];
    const int4 q1 = ((const int4*)labels_raw)[1];

    // Speculative i32 label: word s (in-bounds under both layouts).
    const int li32 = ((const int*)labels_raw)[s];

    // x loads: independent of labels, issued before the predicate resolves.
    const float4* xr = (const float4*)(x + (size_t)s * FEAT_DIM);
    float4 a0 = xr[lane];
    float4 a1 = xr[lane + 32];

    const bool is_i64 = ((q0.y | q0.w | q1.y | q1.w) == 0);
    int lbl;
    if (is_i64) lbl = (int)((const long long*)labels_raw)[s];
    else        lbl = li32;

    const float4* cr = (const float4*)(centers + (size_t)lbl * FEAT_DIM);
    float4 b0 = cr[lane];
    float4 b1 = cr[lane + 32];

    // Two independent FMA chains, then combine.
    float accA = 0.0f, accB = 0.0f, d;
    d = a0.x - b0.x; accA = fmaf(d, d, accA);
    d = a0.y - b0.y; accB = fmaf(d, d, accB);
    d = a0.z - b0.z; accA = fmaf(d, d, accA);
    d = a0.w - b0.w; accB = fmaf(d, d, accB);
    d = a1.x - b1.x; accA = fmaf(d, d, accA);
    d = a1.y - b1.y; accB = fmaf(d, d, accB);
    d = a1.z - b1.z; accA = fmaf(d, d, accA);
    d = a1.w - b1.w; accB = fmaf(d, d, accB);
    float acc = accA + accB;

    // ---- single-instruction warp reduction in u32 fixed point (2^16).
    // Per-lane values < ~2^26; warp sum < 2^31 — no overflow.
    unsigned int lfix = __float2uint_rn(acc * LSCALE);
    unsigned int wsum = __reduce_add_sync(0xFFFFFFFFu, lfix);

    if (lane == 0) {
        // Per-sample clamp (faithful to reference), then 2^24 fixed point.
        double v = (double)wsum * (1.0 / 65536.0);
        v = fmin(fmax(v, 1e-12), 1e12);
        unsigned long long p = (unsigned long long)(v * SCALE);

        // Packed smem atomic: add sum + bump warp count in one op.
        unsigned long long old = atomicAdd(&cta_acc, p + (1ull << CNT_SHIFT));
        if ((old >> CNT_SHIFT) == 7) {
            // Last warp of this CTA: ATOMS return already holds the CTA sum.
            unsigned long long csum = (old & SUM_MASK) + p;

            // Packed global atomic: add CTA sum + bump CTA count.
            unsigned long long gold =
                atomicAdd(&g_acc, csum + (1ull << CNT_SHIFT));
            if ((gold >> CNT_SHIFT) == NBLOCKS - 1) {
                unsigned long long total = (gold & SUM_MASK) + csum;
                double loss = ((double)total / SCALE) / (double)BATCH
                            + (double)(NUM_CLASSES - 1) * 1e-12;
                out[0] = (float)loss;
                g_acc = 0ull;   // reset for next graph replay
            }
        }
    }
}

extern "C" void kernel_launch(void* const* d_in, const int* in_sizes, int n_in,
                              void* d_out, int out_size)
{
    const float* x       = (const float*)d_in[0];
    const void*  labels  = d_in[1];
    const float* centers = (const float*)d_in[2];
    float*       out     = (float*)d_out;
    (void)in_sizes; (void)n_in; (void)out_size;

    center_loss_fused<<<NBLOCKS, NTHREADS>>>(x, labels, centers, out);
}

// round 10
// speedup vs baseline: 1.3527x; 1.3527x over previous
#include <cuda_runtime.h>
#include <cstdint>

// CenterLoss: BATCH=4096, FEAT_DIM=256, NUM_CLASSES=8192
#define BATCH       4096
#define FEAT_DIM    256
#define NUM_CLASSES 8192
#define NBLOCKS     512
#define NTHREADS    256            // 8 warps/CTA, warp-per-sample
#define SCALEF      16777216.0f    // 2^24 fixed-point scale (float convert)
#define SCALE       16777216.0     // same, double (final math)
#define CNT_SHIFT   50             // count lives in bits [50..63]
#define SUM_MASK    ((1ull << CNT_SHIFT) - 1ull)

// Single packed global accumulator: bits [0,50) sum, bits [50,64) CTA count.
__device__ unsigned long long g_acc = 0ull;

__global__ void __launch_bounds__(NTHREADS) center_loss_fused(
    const float* __restrict__ x,
    const void*  __restrict__ labels_raw,
    const float* __restrict__ centers,
    float*       __restrict__ out)
{
    const int lane = threadIdx.x & 31;
    const int warp = threadIdx.x >> 5;            // 0..7
    const int s    = blockIdx.x * 8 + warp;       // sample id 0..4095

    // ---- dtype probe: words 0..7 (one 128B line, warp-uniform -> L2
    // broadcast; concurrent with label + x loads). i64 => odd words zero.
    // False-i64 under i32: labels[1,3,5,7]==0, p = 8192^-4 ~ 2e-16.
    const int4 q0 = ((const int4*)labels_raw)[0];
    const int4 q1 = ((const int4*)labels_raw)[1];

    // Speculative i32 label: word s (in-bounds under both layouts).
    const int li32 = ((const int*)labels_raw)[s];

    // x loads: independent of labels, issued before the predicate resolves.
    const float4* xr = (const float4*)(x + (size_t)s * FEAT_DIM);
    float4 a0 = xr[lane];
    float4 a1 = xr[lane + 32];

    const bool is_i64 = ((q0.y | q0.w | q1.y | q1.w) == 0);
    int lbl;
    if (is_i64) lbl = (int)((const long long*)labels_raw)[s];
    else        lbl = li32;

    const float4* cr = (const float4*)(centers + (size_t)lbl * FEAT_DIM);
    float4 b0 = cr[lane];
    float4 b1 = cr[lane + 32];

    // Two independent FMA chains, then combine.
    float accA = 0.0f, accB = 0.0f, d;
    d = a0.x - b0.x; accA = fmaf(d, d, accA);
    d = a0.y - b0.y; accB = fmaf(d, d, accB);
    d = a0.z - b0.z; accA = fmaf(d, d, accA);
    d = a0.w - b0.w; accB = fmaf(d, d, accB);
    d = a1.x - b1.x; accA = fmaf(d, d, accA);
    d = a1.y - b1.y; accB = fmaf(d, d, accB);
    d = a1.z - b1.z; accA = fmaf(d, d, accA);
    d = a1.w - b1.w; accB = fmaf(d, d, accB);
    float acc = accA + accB;

#pragma unroll
    for (int o = 16; o > 0; o >>= 1)
        acc += __shfl_xor_sync(0xFFFFFFFFu, acc, o);

    // ---- per-CTA tail (R7 structure: smem tree + warp0 combine)
    __shared__ float sh[8];
    if (lane == 0) sh[warp] = fminf(fmaxf(acc, 1e-12f), 1e12f);
    __syncthreads();

    if (warp == 0) {
        unsigned long long p = 0ull;
        if (lane < 8)
            p = (unsigned long long)(sh[lane] * SCALEF);
#pragma unroll
        for (int o = 4; o > 0; o >>= 1)
            p += __shfl_xor_sync(0xFFFFFFFFu, p, o);

        if (lane == 0) {
            // One packed atomic: add CTA sum and bump CTA count.
            unsigned long long gold =
                atomicAdd(&g_acc, p + (1ull << CNT_SHIFT));
            if ((gold >> CNT_SHIFT) == NBLOCKS - 1) {
                unsigned long long total = (gold & SUM_MASK) + p;
                double loss = ((double)total / SCALE) / (double)BATCH
                            + (double)(NUM_CLASSES - 1) * 1e-12;
                out[0] = (float)loss;
                g_acc = 0ull;   // reset for next graph replay
            }
        }
    }
}

extern "C" void kernel_launch(void* const* d_in, const int* in_sizes, int n_in,
                              void* d_out, int out_size)
{
    const float* x       = (const float*)d_in[0];
    const void*  labels  = d_in[1];
    const float* centers = (const float*)d_in[2];
    float*       out     = (float*)d_out;
    (void)in_sizes; (void)n_in; (void)out_size;

    center_loss_fused<<<NBLOCKS, NTHREADS>>>(x, labels, centers, out);
}